// round 1
// baseline (speedup 1.0000x reference)
#include <cuda_runtime.h>
#include <math.h>

#define BATCH 16
#define NPTS  1024
#define KNN_K 20
#define BNSC  0.9999950000374997f   // 1/sqrt(1+1e-5)

// ---------------- scratch (static device globals; no allocs) ----------------
__device__ float g_xx  [BATCH * NPTS];
__device__ float g_dist[(size_t)BATCH * NPTS * NPTS];          // 67 MB
__device__ int   g_idx [BATCH * NPTS * KNN_K];
__device__ float g_A   [(size_t)BATCH * 256 * NPTS];           // 16.8 MB
__device__ float g_Bc  [(size_t)BATCH * 256 * NPTS];           // 16.8 MB
__device__ float g_h   [(size_t)BATCH * 512 * NPTS];           // 33.5 MB (x1|x2|x3|x4)
__device__ float g_y   [(size_t)BATCH * 1024 * NPTS];          // 67 MB
__device__ float g_p   [BATCH * 2048];

// ---------------- xx[b,n] = sum_c x^2 ----------------
__global__ void xx_kernel(const float* __restrict__ x, int C, int bstride) {
    int n = blockIdx.x * 256 + threadIdx.x;
    int b = blockIdx.y;
    const float* xb = x + (size_t)b * bstride;
    float s = 0.f;
    for (int c = 0; c < C; c++) { float v = xb[c * NPTS + n]; s += v * v; }
    g_xx[b * NPTS + n] = s;
}

// ---------------- dist[b,n,m] = 2<x_n,x_m> - xx_n - xx_m ----------------
__global__ void dist_kernel(const float* __restrict__ x, int C, int bstride) {
    int b  = blockIdx.z;
    int m0 = blockIdx.x * 16, n0 = blockIdx.y * 16;
    int tx = threadIdx.x, ty = threadIdx.y;
    const float* xb = x + (size_t)b * bstride;
    __shared__ float Xn[16][17], Xm[16][17];
    float acc = 0.f;
    for (int c0 = 0; c0 < C; c0 += 16) {
        int c = c0 + ty;
        Xn[ty][tx] = (c < C) ? xb[c * NPTS + n0 + tx] : 0.f;
        Xm[ty][tx] = (c < C) ? xb[c * NPTS + m0 + tx] : 0.f;
        __syncthreads();
        #pragma unroll
        for (int cc = 0; cc < 16; cc++) acc += Xn[cc][ty] * Xm[cc][tx];
        __syncthreads();
    }
    float d = 2.f * acc - g_xx[b * NPTS + n0 + ty] - g_xx[b * NPTS + m0 + tx];
    g_dist[((size_t)b * NPTS + n0 + ty) * NPTS + m0 + tx] = d;
}

// ---------------- top-k (k=20) per row, lowest-index tie-break ----------------
__global__ void topk_kernel() {
    int n = blockIdx.x, b = blockIdx.y, t = threadIdx.x;
    int lane = t & 31, w = t >> 5;
    __shared__ float sd[NPTS];
    __shared__ float wv[8];
    __shared__ int   wi[8];
    const float* row = g_dist + ((size_t)b * NPTS + n) * NPTS;
    for (int i = t; i < NPTS; i += 256) sd[i] = row[i];
    __syncthreads();
    int* outp = g_idx + ((size_t)b * NPTS + n) * KNN_K;
    for (int kk = 0; kk < KNN_K; kk++) {
        float bv = -INFINITY; int bi = NPTS;
        for (int i = t; i < NPTS; i += 256) {
            float v = sd[i];
            if (v > bv || (v == bv && i < bi)) { bv = v; bi = i; }
        }
        #pragma unroll
        for (int off = 16; off; off >>= 1) {
            float ov = __shfl_down_sync(0xffffffffu, bv, off);
            int   oi = __shfl_down_sync(0xffffffffu, bi, off);
            if (ov > bv || (ov == bv && oi < bi)) { bv = ov; bi = oi; }
        }
        if (lane == 0) { wv[w] = bv; wi[w] = bi; }
        __syncthreads();
        if (t == 0) {
            for (int j = 1; j < 8; j++)
                if (wv[j] > bv || (wv[j] == bv && wi[j] < bi)) { bv = wv[j]; bi = wi[j]; }
            outp[kk] = bi;
            sd[bi] = -INFINITY;
        }
        __syncthreads();
    }
}

// ---------------- A' = s*(wd x), B' = s*((wc-wd) x) + bias,  s = g*BNS ----------------
__global__ void gemmAB_kernel(const float* __restrict__ x, int C, int bstride, int O,
                              const float* __restrict__ w, const float* __restrict__ g,
                              const float* __restrict__ bias) {
    int n = blockIdx.x * 128 + threadIdx.x;
    int o = blockIdx.y, b = blockIdx.z;
    const float* xb = x + (size_t)b * bstride;
    const float* wd = w + (size_t)o * 2 * C;
    const float* wc = wd + C;
    float a = 0.f, bb = 0.f;
    for (int c = 0; c < C; c++) {
        float xv = xb[c * NPTS + n];
        a  += wd[c] * xv;
        bb += (wc[c] - wd[c]) * xv;
    }
    float s = g[o] * BNSC;
    g_A [((size_t)b * 256 + o) * NPTS + n] = s * a;
    g_Bc[((size_t)b * 256 + o) * NPTS + n] = s * bb + bias[o];
}

// ---------------- out[b,o,n] = leaky( max_k (A'[o,idx[n,k]] + B'[o,n]) ) ----------------
__global__ void gather_kernel(int O, int choff) {
    int n = blockIdx.x * 256 + threadIdx.x;
    int o = blockIdx.y, b = blockIdx.z;
    const float* Ab = g_A + ((size_t)b * 256 + o) * NPTS;
    float bb = g_Bc[((size_t)b * 256 + o) * NPTS + n];
    const int* ip = g_idx + ((size_t)b * NPTS + n) * KNN_K;
    float m = -INFINITY;
    #pragma unroll
    for (int k = 0; k < KNN_K; k++) {
        float v = Ab[ip[k]] + bb;
        m = fmaxf(m, v);
    }
    float r = m > 0.f ? m : 0.2f * m;
    g_h[((size_t)b * 512 + (choff + o)) * NPTS + n] = r;
}

// ---------------- stage 5: y = leaky(bn(w5 @ h)), tiled 64x64 fp32 GEMM ----------------
__global__ void gemm5_kernel(const float* __restrict__ w5, const float* __restrict__ g5,
                             const float* __restrict__ b5) {
    int b = blockIdx.z;
    int o0 = blockIdx.y * 64, n0 = blockIdx.x * 64;
    int t = threadIdx.x;
    int tx = t & 15, ty = t >> 4;
    __shared__ float Ws[16][65], Hs[16][65];
    float acc[4][4] = {};
    const float* hb = g_h + (size_t)b * 512 * NPTS;
    for (int c0 = 0; c0 < 512; c0 += 16) {
        #pragma unroll
        for (int i = 0; i < 4; i++) {
            int idx = t + i * 256;
            int oo = idx >> 4, cc = idx & 15;
            Ws[cc][oo] = w5[(size_t)(o0 + oo) * 512 + c0 + cc];
            int cc2 = idx >> 6, nn = idx & 63;
            Hs[cc2][nn] = hb[(size_t)(c0 + cc2) * NPTS + n0 + nn];
        }
        __syncthreads();
        #pragma unroll
        for (int cc = 0; cc < 16; cc++) {
            float av[4], bv[4];
            #pragma unroll
            for (int i = 0; i < 4; i++) { av[i] = Ws[cc][ty + 16 * i]; bv[i] = Hs[cc][tx + 16 * i]; }
            #pragma unroll
            for (int i = 0; i < 4; i++)
                #pragma unroll
                for (int j = 0; j < 4; j++) acc[i][j] += av[i] * bv[j];
        }
        __syncthreads();
    }
    #pragma unroll
    for (int i = 0; i < 4; i++) {
        int o = o0 + ty + 16 * i;
        float s = g5[o] * BNSC, bi = b5[o];
        #pragma unroll
        for (int j = 0; j < 4; j++) {
            int n = n0 + tx + 16 * j;
            float v = s * acc[i][j] + bi;
            v = v > 0.f ? v : 0.2f * v;
            g_y[((size_t)b * 1024 + o) * NPTS + n] = v;
        }
    }
}

// ---------------- pooling: p[b,0:1024]=max_n y, p[b,1024:2048]=mean_n y ----------------
__global__ void pool_kernel() {
    int o = blockIdx.x, b = blockIdx.y, t = threadIdx.x;
    const float* yr = g_y + ((size_t)b * 1024 + o) * NPTS;
    float mx = -INFINITY, sm = 0.f;
    for (int i = t; i < NPTS; i += 256) { float v = yr[i]; mx = fmaxf(mx, v); sm += v; }
    #pragma unroll
    for (int off = 16; off; off >>= 1) {
        mx = fmaxf(mx, __shfl_down_sync(0xffffffffu, mx, off));
        sm += __shfl_down_sync(0xffffffffu, sm, off);
    }
    __shared__ float smx[8], ssm[8];
    if ((t & 31) == 0) { smx[t >> 5] = mx; ssm[t >> 5] = sm; }
    __syncthreads();
    if (t == 0) {
        for (int j = 1; j < 8; j++) { mx = fmaxf(mx, smx[j]); sm += ssm[j]; }
        g_p[b * 2048 + o] = mx;
        g_p[b * 2048 + 1024 + o] = sm * (1.f / NPTS);
    }
}

// ---------------- MLP head: one block per batch ----------------
__global__ void head_kernel(const float* __restrict__ wl1, const float* __restrict__ g6, const float* __restrict__ b6,
                            const float* __restrict__ wl2, const float* __restrict__ g7, const float* __restrict__ b7,
                            const float* __restrict__ wl21, const float* __restrict__ wl22,
                            const float* __restrict__ g8, const float* __restrict__ b8,
                            const float* __restrict__ wl3, float* __restrict__ out) {
    int b = blockIdx.x, t = threadIdx.x;
    __shared__ float sp[2048], s1[256], s2[128], s3[64], s4[32];
    for (int i = t; i < 2048; i += 256) sp[i] = g_p[b * 2048 + i];
    __syncthreads();
    {   // z1 = leaky(bn(p @ wl1^T))  (256 outputs)
        float acc = 0.f;
        const float* wr = wl1 + (size_t)t * 2048;
        for (int c = 0; c < 2048; c++) acc += sp[c] * wr[c];
        acc = g6[t] * (acc * BNSC) + b6[t];
        s1[t] = acc > 0.f ? acc : 0.2f * acc;
    }
    __syncthreads();
    if (t < 128) {  // z2 (128)
        float acc = 0.f;
        const float* wr = wl2 + (size_t)t * 256;
        for (int c = 0; c < 256; c++) acc += s1[c] * wr[c];
        acc = g7[t] * (acc * BNSC) + b7[t];
        s2[t] = acc > 0.f ? acc : 0.2f * acc;
    }
    __syncthreads();
    if (t < 64) {   // t3 = z2 @ wl21^T (no bn/act)
        float acc = 0.f;
        const float* wr = wl21 + (size_t)t * 128;
        for (int c = 0; c < 128; c++) acc += s2[c] * wr[c];
        s3[t] = acc;
    }
    __syncthreads();
    if (t < 32) {   // z4 = gelu(bn(t3 @ wl22^T))
        float acc = 0.f;
        const float* wr = wl22 + (size_t)t * 64;
        for (int c = 0; c < 64; c++) acc += s3[c] * wr[c];
        acc = g8[t] * (acc * BNSC) + b8[t];
        s4[t] = 0.5f * acc * (1.0f + erff(acc * 0.70710678118654752f));
    }
    __syncthreads();
    if (t < 90) {   // out = z4 @ wl3^T
        float acc = 0.f;
        const float* wr = wl3 + (size_t)t * 32;
        for (int c = 0; c < 32; c++) acc += s4[c] * wr[c];
        out[b * 90 + t] = acc;
    }
}

// ---------------- launcher ----------------
extern "C" void kernel_launch(void* const* d_in, const int* in_sizes, int n_in,
                              void* d_out, int out_size) {
    const float* x   = (const float*)d_in[0];
    const float* w1  = (const float*)d_in[2];
    const float* g1  = (const float*)d_in[3];
    const float* b1  = (const float*)d_in[4];
    const float* w2  = (const float*)d_in[5];
    const float* g2  = (const float*)d_in[6];
    const float* b2  = (const float*)d_in[7];
    const float* w3  = (const float*)d_in[8];
    const float* g3  = (const float*)d_in[9];
    const float* b3  = (const float*)d_in[10];
    const float* w4  = (const float*)d_in[11];
    const float* g4  = (const float*)d_in[12];
    const float* b4  = (const float*)d_in[13];
    const float* w5  = (const float*)d_in[14];
    const float* g5  = (const float*)d_in[15];
    const float* b5  = (const float*)d_in[16];
    const float* wl1 = (const float*)d_in[17];
    const float* g6  = (const float*)d_in[18];
    const float* b6  = (const float*)d_in[19];
    const float* wl2 = (const float*)d_in[20];
    const float* g7  = (const float*)d_in[21];
    const float* b7  = (const float*)d_in[22];
    const float* wl21= (const float*)d_in[23];
    const float* wl22= (const float*)d_in[24];
    const float* g8  = (const float*)d_in[25];
    const float* b8  = (const float*)d_in[26];
    const float* wl3 = (const float*)d_in[27];

    float* gh = nullptr;
    cudaGetSymbolAddress((void**)&gh, g_h);

    struct St { const float* in; int C; int bstride; int O;
                const float* w; const float* g; const float* bb; int choff; };
    St st[4] = {
        { x,               6,   6 * NPTS,   64,  w1, g1, b1, 0   },
        { gh,              64,  512 * NPTS, 64,  w2, g2, b2, 64  },
        { gh + 64 * NPTS,  64,  512 * NPTS, 128, w3, g3, b3, 128 },
        { gh + 128 * NPTS, 128, 512 * NPTS, 256, w4, g4, b4, 256 },
    };

    for (int s = 0; s < 4; s++) {
        xx_kernel  <<<dim3(NPTS / 256, BATCH), 256>>>(st[s].in, st[s].C, st[s].bstride);
        dist_kernel<<<dim3(64, 64, BATCH), dim3(16, 16)>>>(st[s].in, st[s].C, st[s].bstride);
        topk_kernel<<<dim3(NPTS, BATCH), 256>>>();
        gemmAB_kernel<<<dim3(NPTS / 128, st[s].O, BATCH), 128>>>(
            st[s].in, st[s].C, st[s].bstride, st[s].O, st[s].w, st[s].g, st[s].bb);
        gather_kernel<<<dim3(NPTS / 256, st[s].O, BATCH), 256>>>(st[s].O, st[s].choff);
    }

    gemm5_kernel<<<dim3(16, 16, BATCH), 256>>>(w5, g5, b5);
    pool_kernel <<<dim3(1024, BATCH), 256>>>();
    head_kernel <<<BATCH, 256>>>(wl1, g6, b6, wl2, g7, b7, wl21, wl22, g8, b8, wl3,
                                 (float*)d_out);
}

// round 2
// speedup vs baseline: 2.1601x; 2.1601x over previous
#include <cuda_runtime.h>
#include <math.h>

#define BATCH 16
#define NPTS  1024
#define KNN_K 20
#define BNSC  0.9999950000374997f   // 1/sqrt(1+1e-5)

typedef unsigned long long ull;

// ---------------- scratch (static device globals; no allocs) ----------------
__device__ float g_xx  [BATCH * NPTS];
__device__ float g_dist[(size_t)BATCH * NPTS * NPTS];          // 67 MB
__device__ int   g_idx [BATCH * NPTS * KNN_K];
__device__ float g_A   [(size_t)BATCH * NPTS * 256];           // [b][n][O]
__device__ float g_Bc  [(size_t)BATCH * NPTS * 256];           // [b][n][O]
__device__ float g_h   [(size_t)BATCH * NPTS * 512];           // [b][n][512]
__device__ float g_y   [(size_t)BATCH * 1024 * NPTS];          // [b][o][n]
__device__ float g_p   [BATCH * 2048];

// ---------------- f32x2 packed helpers ----------------
__device__ __forceinline__ ull pk2(float a, float b) {
    ull r; asm("mov.b64 %0, {%1, %2};" : "=l"(r) : "f"(a), "f"(b)); return r;
}
__device__ __forceinline__ void ffma2(ull& d, ull a, ull b) {
    asm("fma.rn.f32x2 %0, %1, %2, %0;" : "+l"(d) : "l"(a), "l"(b));
}

// ---------------- xx: sum of squares per point ----------------
__global__ void xx_cn_kernel(const float* __restrict__ x, int C) {
    int n = blockIdx.x * 256 + threadIdx.x;
    int b = blockIdx.y;
    const float* xb = x + (size_t)b * C * NPTS;
    float s = 0.f;
    for (int c = 0; c < C; c++) { float v = xb[c * NPTS + n]; s += v * v; }
    g_xx[b * NPTS + n] = s;
}
__global__ void xx_nc_kernel(const float* __restrict__ h, int coff, int C) {
    int rid = blockIdx.x * 8 + (threadIdx.x >> 5);
    int lane = threadIdx.x & 31;
    const float* p = h + (size_t)rid * 512 + coff;
    float s = 0.f;
    for (int c = lane; c < C; c += 32) { float v = p[c]; s += v * v; }
    #pragma unroll
    for (int off = 16; off; off >>= 1) s += __shfl_down_sync(0xffffffffu, s, off);
    if (lane == 0) g_xx[rid] = s;
}

// ---------------- dist: 128x128 tile, FFMA2 register-blocked ----------------
__global__ void dist_kernel(const float* __restrict__ x, int cn, int coff, int C) {
    __shared__ float Xn[16][132], Xm[16][132];
    int b = blockIdx.z;
    int m0 = blockIdx.x * 128, n0 = blockIdx.y * 128;
    int t = threadIdx.x, tx = t & 15, ty = t >> 4;
    ull acc[8][4];
    #pragma unroll
    for (int i = 0; i < 8; i++)
        #pragma unroll
        for (int j = 0; j < 4; j++) acc[i][j] = 0ull;

    for (int c0 = 0; c0 < C; c0 += 16) {
        __syncthreads();
        if (cn) {
            #pragma unroll
            for (int i = 0; i < 8; i++) {
                int idx = t + i * 256;
                int cc = idx >> 7, nn = idx & 127;
                int c = c0 + cc;
                float vn = 0.f, vm = 0.f;
                if (c < C) {
                    const float* xb = x + (size_t)b * C * NPTS + (size_t)c * NPTS;
                    vn = xb[n0 + nn]; vm = xb[m0 + nn];
                }
                Xn[cc][nn] = vn; Xm[cc][nn] = vm;
            }
        } else {
            int nn = t >> 1, cs = (t & 1) * 8;
            const float* pn = x + ((size_t)(b * NPTS) + n0 + nn) * 512 + coff + c0 + cs;
            const float* pm = x + ((size_t)(b * NPTS) + m0 + nn) * 512 + coff + c0 + cs;
            float4 a0 = *(const float4*)pn, a1 = *(const float4*)(pn + 4);
            float4 b0 = *(const float4*)pm, b1 = *(const float4*)(pm + 4);
            Xn[cs + 0][nn] = a0.x; Xn[cs + 1][nn] = a0.y; Xn[cs + 2][nn] = a0.z; Xn[cs + 3][nn] = a0.w;
            Xn[cs + 4][nn] = a1.x; Xn[cs + 5][nn] = a1.y; Xn[cs + 6][nn] = a1.z; Xn[cs + 7][nn] = a1.w;
            Xm[cs + 0][nn] = b0.x; Xm[cs + 1][nn] = b0.y; Xm[cs + 2][nn] = b0.z; Xm[cs + 3][nn] = b0.w;
            Xm[cs + 4][nn] = b1.x; Xm[cs + 5][nn] = b1.y; Xm[cs + 6][nn] = b1.z; Xm[cs + 7][nn] = b1.w;
        }
        __syncthreads();
        #pragma unroll
        for (int cc = 0; cc < 16; cc++) {
            ull a2[8], b2[4];
            #pragma unroll
            for (int i = 0; i < 8; i++) { float av = Xn[cc][ty + 16 * i]; a2[i] = pk2(av, av); }
            #pragma unroll
            for (int j = 0; j < 4; j++) b2[j] = *(const ull*)&Xm[cc][2 * tx + 32 * j];
            #pragma unroll
            for (int i = 0; i < 8; i++)
                #pragma unroll
                for (int j = 0; j < 4; j++) ffma2(acc[i][j], a2[i], b2[j]);
        }
    }
    #pragma unroll
    for (int i = 0; i < 8; i++) {
        int n = n0 + ty + 16 * i;
        float xn = g_xx[b * NPTS + n];
        float* drow = g_dist + ((size_t)(b * NPTS) + n) * NPTS;
        #pragma unroll
        for (int j = 0; j < 4; j++) {
            int m = m0 + 2 * tx + 32 * j;
            float2 v = *(float2*)&acc[i][j];
            float2 xm = *(const float2*)&g_xx[b * NPTS + m];
            float2 o;
            o.x = 2.f * v.x - xn - xm.x;
            o.y = 2.f * v.y - xn - xm.y;
            *(float2*)&drow[m] = o;
        }
    }
}

// ---------------- top-k: warp per row, shuffle-only ----------------
__global__ void topk_kernel() {
    __shared__ float sd[8][NPTS];
    int w = threadIdx.x >> 5, lane = threadIdx.x & 31;
    int rid = blockIdx.x * 8 + w;
    const float* row = g_dist + (size_t)rid * NPTS;
    float* s = sd[w];
    for (int i = lane; i < NPTS; i += 32) s[i] = row[i];
    __syncwarp();
    int* outp = g_idx + (size_t)rid * KNN_K;
    for (int kk = 0; kk < KNN_K; kk++) {
        float bv = -INFINITY; int bi = NPTS;
        for (int j = lane; j < NPTS; j += 32) {
            float v = s[j];
            if (v > bv || (v == bv && j < bi)) { bv = v; bi = j; }
        }
        #pragma unroll
        for (int off = 16; off; off >>= 1) {
            float ov = __shfl_down_sync(0xffffffffu, bv, off);
            int   oi = __shfl_down_sync(0xffffffffu, bi, off);
            if (ov > bv || (ov == bv && oi < bi)) { bv = ov; bi = oi; }
        }
        bi = __shfl_sync(0xffffffffu, bi, 0);
        if (lane == 0) outp[kk] = bi;
        if (lane == (bi & 31)) s[bi] = -INFINITY;
        __syncwarp();
    }
}

// ---------------- gemmAB: 64(o) x 64(n) tile, writes [n][o] ----------------
__global__ void gemmAB_kernel(const float* __restrict__ x, int cn, int coff, int C, int O,
                              const float* __restrict__ w, const float* __restrict__ g,
                              const float* __restrict__ bias) {
    __shared__ float Wd[16][68], Wl[16][68], Xs[16][68];
    int b = blockIdx.z;
    int o0 = blockIdx.y * 64, n0 = blockIdx.x * 64;
    int t = threadIdx.x, tx = t & 15, ty = t >> 4;
    float aA[4][4] = {}, aB[4][4] = {};
    for (int c0 = 0; c0 < C; c0 += 16) {
        __syncthreads();
        #pragma unroll
        for (int i = 0; i < 4; i++) {
            int idx = t + i * 256;
            int oo = idx >> 4, cc = idx & 15;
            int c = c0 + cc;
            float wd = 0.f, wc = 0.f;
            if (c < C) {
                wd = w[(size_t)(o0 + oo) * 2 * C + c];
                wc = w[(size_t)(o0 + oo) * 2 * C + C + c];
            }
            Wd[cc][oo] = wd; Wl[cc][oo] = wc - wd;
            if (cn) {
                int cc2 = idx >> 6, nn = idx & 63;
                int c2 = c0 + cc2;
                float xv = (c2 < C) ? x[(size_t)b * C * NPTS + (size_t)c2 * NPTS + n0 + nn] : 0.f;
                Xs[cc2][nn] = xv;
            } else {
                int nn = idx >> 4, cc3 = idx & 15;
                int c3 = c0 + cc3;
                float xv = (c3 < C) ? x[((size_t)(b * NPTS) + n0 + nn) * 512 + coff + c3] : 0.f;
                Xs[cc3][nn] = xv;
            }
        }
        __syncthreads();
        #pragma unroll
        for (int cc = 0; cc < 16; cc++) {
            float wa[4], wl[4], xv[4];
            #pragma unroll
            for (int i = 0; i < 4; i++) { wa[i] = Wd[cc][tx + 16 * i]; wl[i] = Wl[cc][tx + 16 * i]; }
            #pragma unroll
            for (int j = 0; j < 4; j++) xv[j] = Xs[cc][ty + 16 * j];
            #pragma unroll
            for (int i = 0; i < 4; i++)
                #pragma unroll
                for (int j = 0; j < 4; j++) { aA[i][j] += wa[i] * xv[j]; aB[i][j] += wl[i] * xv[j]; }
        }
    }
    #pragma unroll
    for (int i = 0; i < 4; i++) {
        int o = o0 + tx + 16 * i;
        float s = g[o] * BNSC, bo = bias[o];
        #pragma unroll
        for (int j = 0; j < 4; j++) {
            int n = n0 + ty + 16 * j;
            size_t base = ((size_t)(b * NPTS) + n) * O + o;
            g_A[base]  = s * aA[i][j];
            g_Bc[base] = s * aB[i][j] + bo;
        }
    }
}

// ---------------- gather: warp per point, coalesced A rows ----------------
__global__ void gather_kernel(int O, int choff) {
    int w = threadIdx.x >> 5, lane = threadIdx.x & 31;
    int n = blockIdx.x * 8 + w;
    int b = blockIdx.y;
    size_t rowi = (size_t)(b * NPTS) + n;
    const int* ip = g_idx + rowi * KNN_K;
    int iv = (lane < KNN_K) ? ip[lane] : 0;
    int O4 = O >> 2;
    const float4* A4 = (const float4*)g_A + (size_t)(b * NPTS) * O4;
    int npass = (O + 127) / 128;
    for (int p = 0; p < npass; p++) {
        int o4 = p * 128 + lane * 4;
        bool act = o4 < O;
        float4 m = make_float4(-INFINITY, -INFINITY, -INFINITY, -INFINITY);
        #pragma unroll
        for (int k = 0; k < KNN_K; k++) {
            int j = __shfl_sync(0xffffffffu, iv, k);
            if (act) {
                float4 a = A4[(size_t)j * O4 + (o4 >> 2)];
                m.x = fmaxf(m.x, a.x); m.y = fmaxf(m.y, a.y);
                m.z = fmaxf(m.z, a.z); m.w = fmaxf(m.w, a.w);
            }
        }
        if (act) {
            float4 bb = *(const float4*)&g_Bc[rowi * O + o4];
            float4 r;
            r.x = m.x + bb.x; r.y = m.y + bb.y; r.z = m.z + bb.z; r.w = m.w + bb.w;
            r.x = r.x > 0.f ? r.x : 0.2f * r.x;
            r.y = r.y > 0.f ? r.y : 0.2f * r.y;
            r.z = r.z > 0.f ? r.z : 0.2f * r.z;
            r.w = r.w > 0.f ? r.w : 0.2f * r.w;
            *(float4*)&g_h[rowi * 512 + choff + o4] = r;
        }
    }
}

// ---------------- gemm5: 128x128 tile, FFMA2 ----------------
__global__ void gemm5_kernel(const float* __restrict__ w5, const float* __restrict__ g5,
                             const float* __restrict__ b5) {
    __shared__ float Ws[16][132], Hs[16][132];
    int b = blockIdx.z;
    int o0 = blockIdx.y * 128, n0 = blockIdx.x * 128;
    int t = threadIdx.x, tx = t & 15, ty = t >> 4;
    ull acc[8][4];
    #pragma unroll
    for (int i = 0; i < 8; i++)
        #pragma unroll
        for (int j = 0; j < 4; j++) acc[i][j] = 0ull;

    int nn = t >> 1, cs = (t & 1) * 8;
    const float* hrow = g_h + ((size_t)(b * NPTS) + n0 + nn) * 512 + cs;
    const float* wrow = w5 + (size_t)(o0 + nn) * 512 + cs;
    for (int c0 = 0; c0 < 512; c0 += 16) {
        float4 w0 = *(const float4*)(wrow + c0), w1 = *(const float4*)(wrow + c0 + 4);
        float4 h0 = *(const float4*)(hrow + c0), h1 = *(const float4*)(hrow + c0 + 4);
        __syncthreads();
        Ws[cs + 0][nn] = w0.x; Ws[cs + 1][nn] = w0.y; Ws[cs + 2][nn] = w0.z; Ws[cs + 3][nn] = w0.w;
        Ws[cs + 4][nn] = w1.x; Ws[cs + 5][nn] = w1.y; Ws[cs + 6][nn] = w1.z; Ws[cs + 7][nn] = w1.w;
        Hs[cs + 0][nn] = h0.x; Hs[cs + 1][nn] = h0.y; Hs[cs + 2][nn] = h0.z; Hs[cs + 3][nn] = h0.w;
        Hs[cs + 4][nn] = h1.x; Hs[cs + 5][nn] = h1.y; Hs[cs + 6][nn] = h1.z; Hs[cs + 7][nn] = h1.w;
        __syncthreads();
        #pragma unroll
        for (int cc = 0; cc < 16; cc++) {
            ull a2[8], b2[4];
            #pragma unroll
            for (int i = 0; i < 8; i++) { float av = Ws[cc][ty + 16 * i]; a2[i] = pk2(av, av); }
            #pragma unroll
            for (int j = 0; j < 4; j++) b2[j] = *(const ull*)&Hs[cc][2 * tx + 32 * j];
            #pragma unroll
            for (int i = 0; i < 8; i++)
                #pragma unroll
                for (int j = 0; j < 4; j++) ffma2(acc[i][j], a2[i], b2[j]);
        }
    }
    #pragma unroll
    for (int i = 0; i < 8; i++) {
        int o = o0 + ty + 16 * i;
        float s = g5[o] * BNSC, bo = b5[o];
        float* yrow = g_y + ((size_t)(b * 1024) + o) * NPTS;
        #pragma unroll
        for (int j = 0; j < 4; j++) {
            int n = n0 + 2 * tx + 32 * j;
            float2 v = *(float2*)&acc[i][j];
            v.x = s * v.x + bo; v.y = s * v.y + bo;
            v.x = v.x > 0.f ? v.x : 0.2f * v.x;
            v.y = v.y > 0.f ? v.y : 0.2f * v.y;
            *(float2*)&yrow[n] = v;
        }
    }
}

// ---------------- pooling ----------------
__global__ void pool_kernel() {
    int o = blockIdx.x, b = blockIdx.y, t = threadIdx.x;
    const float* yr = g_y + ((size_t)(b * 1024) + o) * NPTS;
    float mx = -INFINITY, sm = 0.f;
    for (int i = t; i < NPTS; i += 256) { float v = yr[i]; mx = fmaxf(mx, v); sm += v; }
    #pragma unroll
    for (int off = 16; off; off >>= 1) {
        mx = fmaxf(mx, __shfl_down_sync(0xffffffffu, mx, off));
        sm += __shfl_down_sync(0xffffffffu, sm, off);
    }
    __shared__ float smx[8], ssm[8];
    if ((t & 31) == 0) { smx[t >> 5] = mx; ssm[t >> 5] = sm; }
    __syncthreads();
    if (t == 0) {
        for (int j = 1; j < 8; j++) { mx = fmaxf(mx, smx[j]); sm += ssm[j]; }
        g_p[b * 2048 + o] = mx;
        g_p[b * 2048 + 1024 + o] = sm * (1.f / NPTS);
    }
}

// ---------------- MLP head ----------------
__global__ void head_kernel(const float* __restrict__ wl1, const float* __restrict__ g6, const float* __restrict__ b6,
                            const float* __restrict__ wl2, const float* __restrict__ g7, const float* __restrict__ b7,
                            const float* __restrict__ wl21, const float* __restrict__ wl22,
                            const float* __restrict__ g8, const float* __restrict__ b8,
                            const float* __restrict__ wl3, float* __restrict__ out) {
    int b = blockIdx.x, t = threadIdx.x;
    __shared__ float sp[2048], s1[256], s2[128], s3[64], s4[32];
    for (int i = t; i < 2048; i += 256) sp[i] = g_p[b * 2048 + i];
    __syncthreads();
    {
        float acc = 0.f;
        const float* wr = wl1 + (size_t)t * 2048;
        for (int c = 0; c < 2048; c++) acc += sp[c] * wr[c];
        acc = g6[t] * (acc * BNSC) + b6[t];
        s1[t] = acc > 0.f ? acc : 0.2f * acc;
    }
    __syncthreads();
    if (t < 128) {
        float acc = 0.f;
        const float* wr = wl2 + (size_t)t * 256;
        for (int c = 0; c < 256; c++) acc += s1[c] * wr[c];
        acc = g7[t] * (acc * BNSC) + b7[t];
        s2[t] = acc > 0.f ? acc : 0.2f * acc;
    }
    __syncthreads();
    if (t < 64) {
        float acc = 0.f;
        const float* wr = wl21 + (size_t)t * 128;
        for (int c = 0; c < 128; c++) acc += s2[c] * wr[c];
        s3[t] = acc;
    }
    __syncthreads();
    if (t < 32) {
        float acc = 0.f;
        const float* wr = wl22 + (size_t)t * 64;
        for (int c = 0; c < 64; c++) acc += s3[c] * wr[c];
        acc = g8[t] * (acc * BNSC) + b8[t];
        s4[t] = 0.5f * acc * (1.0f + erff(acc * 0.70710678118654752f));
    }
    __syncthreads();
    if (t < 90) {
        float acc = 0.f;
        const float* wr = wl3 + (size_t)t * 32;
        for (int c = 0; c < 32; c++) acc += s4[c] * wr[c];
        out[b * 90 + t] = acc;
    }
}

// ---------------- launcher ----------------
extern "C" void kernel_launch(void* const* d_in, const int* in_sizes, int n_in,
                              void* d_out, int out_size) {
    const float* x   = (const float*)d_in[0];
    const float* w1  = (const float*)d_in[2];
    const float* g1  = (const float*)d_in[3];
    const float* b1  = (const float*)d_in[4];
    const float* w2  = (const float*)d_in[5];
    const float* g2  = (const float*)d_in[6];
    const float* b2  = (const float*)d_in[7];
    const float* w3  = (const float*)d_in[8];
    const float* g3  = (const float*)d_in[9];
    const float* b3  = (const float*)d_in[10];
    const float* w4  = (const float*)d_in[11];
    const float* g4  = (const float*)d_in[12];
    const float* b4  = (const float*)d_in[13];
    const float* w5  = (const float*)d_in[14];
    const float* g5  = (const float*)d_in[15];
    const float* b5  = (const float*)d_in[16];
    const float* wl1 = (const float*)d_in[17];
    const float* g6  = (const float*)d_in[18];
    const float* b6  = (const float*)d_in[19];
    const float* wl2 = (const float*)d_in[20];
    const float* g7  = (const float*)d_in[21];
    const float* b7  = (const float*)d_in[22];
    const float* wl21= (const float*)d_in[23];
    const float* wl22= (const float*)d_in[24];
    const float* g8  = (const float*)d_in[25];
    const float* b8  = (const float*)d_in[26];
    const float* wl3 = (const float*)d_in[27];

    float* gh = nullptr;
    cudaGetSymbolAddress((void**)&gh, g_h);

    struct St { const float* in; int cn; int coff; int C; int O; int choff;
                const float* w; const float* g; const float* bb; };
    St st[4] = {
        { x,  1, 0,   6,   64,  0,   w1, g1, b1 },
        { gh, 0, 0,   64,  64,  64,  w2, g2, b2 },
        { gh, 0, 64,  64,  128, 128, w3, g3, b3 },
        { gh, 0, 128, 128, 256, 256, w4, g4, b4 },
    };

    for (int s = 0; s < 4; s++) {
        if (st[s].cn)
            xx_cn_kernel<<<dim3(NPTS / 256, BATCH), 256>>>(st[s].in, st[s].C);
        else
            xx_nc_kernel<<<(BATCH * NPTS) / 8, 256>>>(st[s].in, st[s].coff, st[s].C);
        dist_kernel<<<dim3(8, 8, BATCH), 256>>>(st[s].in, st[s].cn, st[s].coff, st[s].C);
        topk_kernel<<<(BATCH * NPTS) / 8, 256>>>();
        gemmAB_kernel<<<dim3(16, st[s].O / 64, BATCH), 256>>>(
            st[s].in, st[s].cn, st[s].coff, st[s].C, st[s].O, st[s].w, st[s].g, st[s].bb);
        gather_kernel<<<dim3(NPTS / 8, BATCH), 256>>>(st[s].O, st[s].choff);
    }

    gemm5_kernel<<<dim3(8, 8, BATCH), 256>>>(w5, g5, b5);
    pool_kernel <<<dim3(1024, BATCH), 256>>>();
    head_kernel <<<BATCH, 256>>>(wl1, g6, b6, wl2, g7, b7, wl21, wl22, g8, b8, wl3,
                                 (float*)d_out);
}

// round 3
// speedup vs baseline: 2.8928x; 1.3392x over previous
#include <cuda_runtime.h>
#include <math.h>

#define BATCH 16
#define NPTS  1024
#define KNN_K 20
#define BNSC  0.9999950000374997f   // 1/sqrt(1+1e-5)

typedef unsigned long long ull;

// ---------------- scratch (static device globals; no allocs) ----------------
__device__ float g_xx  [BATCH * NPTS];
__device__ float g_dist[(size_t)BATCH * NPTS * NPTS];          // 67 MB
__device__ int   g_idx [BATCH * NPTS * KNN_K];
__device__ float g_A   [(size_t)BATCH * NPTS * 256];           // [b][n][O]
__device__ float g_Bc  [(size_t)BATCH * NPTS * 256];           // [b][n][O]
__device__ float g_h   [(size_t)BATCH * NPTS * 512];           // [b][n][512]
__device__ unsigned g_pmax[BATCH * 1024];
__device__ float    g_psum[BATCH * 1024];

// ---------------- helpers ----------------
__device__ __forceinline__ ull pk2(float a, float b) {
    ull r; asm("mov.b64 %0, {%1, %2};" : "=l"(r) : "f"(a), "f"(b)); return r;
}
__device__ __forceinline__ void ffma2(ull& d, ull a, ull b) {
    asm("fma.rn.f32x2 %0, %1, %2, %0;" : "+l"(d) : "l"(a), "l"(b));
}
__device__ __forceinline__ unsigned fenc(float v) {
    unsigned u = __float_as_uint(v);
    return u ^ (((int)u >> 31) | 0x80000000u);
}

// ---------------- xx for stage 1 (raw x, [c][n] layout) ----------------
__global__ void xx_cn_kernel(const float* __restrict__ x) {
    int n = blockIdx.x * 256 + threadIdx.x;
    int b = blockIdx.y;
    const float* xb = x + (size_t)b * 6 * NPTS;
    float s = 0.f;
    #pragma unroll
    for (int c = 0; c < 6; c++) { float v = xb[c * NPTS + n]; s += v * v; }
    g_xx[b * NPTS + n] = s;
}

// ---------------- dist stage 1: C=6, [c][n] input ----------------
__global__ void dist_cn_kernel(const float* __restrict__ x) {
    __shared__ float Xn[6][132], Xm[6][132];
    int b = blockIdx.z;
    int m0 = blockIdx.x * 128, n0 = blockIdx.y * 128;
    int t = threadIdx.x, tx = t & 15, ty = t >> 4;
    ull acc[8][4];
    #pragma unroll
    for (int i = 0; i < 8; i++)
        #pragma unroll
        for (int j = 0; j < 4; j++) acc[i][j] = 0ull;

    for (int idx = t; idx < 6 * 128; idx += 256) {
        int cc = idx >> 7, nn = idx & 127;
        const float* xb = x + (size_t)b * 6 * NPTS + (size_t)cc * NPTS;
        Xn[cc][nn] = xb[n0 + nn];
        Xm[cc][nn] = xb[m0 + nn];
    }
    __syncthreads();
    #pragma unroll
    for (int cc = 0; cc < 6; cc++) {
        ull a2[8], b2[4];
        #pragma unroll
        for (int i = 0; i < 8; i++) { float av = Xn[cc][ty + 16 * i]; a2[i] = pk2(av, av); }
        #pragma unroll
        for (int j = 0; j < 4; j++) b2[j] = *(const ull*)&Xm[cc][2 * tx + 32 * j];
        #pragma unroll
        for (int i = 0; i < 8; i++)
            #pragma unroll
            for (int j = 0; j < 4; j++) ffma2(acc[i][j], a2[i], b2[j]);
    }
    #pragma unroll
    for (int i = 0; i < 8; i++) {
        int n = n0 + ty + 16 * i;
        float xn = g_xx[b * NPTS + n];
        float* drow = g_dist + ((size_t)(b * NPTS) + n) * NPTS;
        #pragma unroll
        for (int j = 0; j < 4; j++) {
            int m = m0 + 2 * tx + 32 * j;
            float2 v = *(float2*)&acc[i][j];
            float2 xm = *(const float2*)&g_xx[b * NPTS + m];
            float2 o;
            o.x = 2.f * v.x - xn - xm.x;
            o.y = 2.f * v.y - xn - xm.y;
            *(float2*)&drow[m] = o;
        }
    }
}

// ---------------- dist stages 2-4: [n][c] input, double-buffered ----------------
__global__ void dist_nc_kernel(const float* __restrict__ h, int coff, int C) {
    __shared__ float Xn[2][16][132], Xm[2][16][132];
    int b = blockIdx.z;
    int m0 = blockIdx.x * 128, n0 = blockIdx.y * 128;
    int t = threadIdx.x, tx = t & 15, ty = t >> 4;
    ull acc[8][4];
    #pragma unroll
    for (int i = 0; i < 8; i++)
        #pragma unroll
        for (int j = 0; j < 4; j++) acc[i][j] = 0ull;

    int nn = t >> 1, cs = (t & 1) * 8;
    const float* pn = h + ((size_t)(b * NPTS) + n0 + nn) * 512 + coff + cs;
    const float* pm = h + ((size_t)(b * NPTS) + m0 + nn) * 512 + coff + cs;
    int K = C >> 4;
    float4 a0, a1, c0r, c1r;

    a0 = *(const float4*)pn;  a1 = *(const float4*)(pn + 4);
    c0r = *(const float4*)pm; c1r = *(const float4*)(pm + 4);
    {
        float* dn = &Xn[0][cs][nn]; float* dm = &Xm[0][cs][nn];
        dn[0*132]=a0.x; dn[1*132]=a0.y; dn[2*132]=a0.z; dn[3*132]=a0.w;
        dn[4*132]=a1.x; dn[5*132]=a1.y; dn[6*132]=a1.z; dn[7*132]=a1.w;
        dm[0*132]=c0r.x; dm[1*132]=c0r.y; dm[2*132]=c0r.z; dm[3*132]=c0r.w;
        dm[4*132]=c1r.x; dm[5*132]=c1r.y; dm[6*132]=c1r.z; dm[7*132]=c1r.w;
    }
    __syncthreads();

    for (int k = 0; k < K; k++) {
        int kn = k + 1;
        if (kn < K) {
            const float* qn = pn + kn * 16;
            const float* qm = pm + kn * 16;
            a0 = *(const float4*)qn;  a1 = *(const float4*)(qn + 4);
            c0r = *(const float4*)qm; c1r = *(const float4*)(qm + 4);
        }
        int p = k & 1;
        #pragma unroll
        for (int cc = 0; cc < 16; cc++) {
            ull a2[8], b2[4];
            #pragma unroll
            for (int i = 0; i < 8; i++) { float av = Xn[p][cc][ty + 16 * i]; a2[i] = pk2(av, av); }
            #pragma unroll
            for (int j = 0; j < 4; j++) b2[j] = *(const ull*)&Xm[p][cc][2 * tx + 32 * j];
            #pragma unroll
            for (int i = 0; i < 8; i++)
                #pragma unroll
                for (int j = 0; j < 4; j++) ffma2(acc[i][j], a2[i], b2[j]);
        }
        if (kn < K) {
            int q = kn & 1;
            float* dn = &Xn[q][cs][nn]; float* dm = &Xm[q][cs][nn];
            dn[0*132]=a0.x; dn[1*132]=a0.y; dn[2*132]=a0.z; dn[3*132]=a0.w;
            dn[4*132]=a1.x; dn[5*132]=a1.y; dn[6*132]=a1.z; dn[7*132]=a1.w;
            dm[0*132]=c0r.x; dm[1*132]=c0r.y; dm[2*132]=c0r.z; dm[3*132]=c0r.w;
            dm[4*132]=c1r.x; dm[5*132]=c1r.y; dm[6*132]=c1r.z; dm[7*132]=c1r.w;
        }
        __syncthreads();
    }
    #pragma unroll
    for (int i = 0; i < 8; i++) {
        int n = n0 + ty + 16 * i;
        float xn = g_xx[b * NPTS + n];
        float* drow = g_dist + ((size_t)(b * NPTS) + n) * NPTS;
        #pragma unroll
        for (int j = 0; j < 4; j++) {
            int m = m0 + 2 * tx + 32 * j;
            float2 v = *(float2*)&acc[i][j];
            float2 xm = *(const float2*)&g_xx[b * NPTS + m];
            float2 o;
            o.x = 2.f * v.x - xn - xm.x;
            o.y = 2.f * v.y - xn - xm.y;
            *(float2*)&drow[m] = o;
        }
    }
}

// ---------------- top-k: per-lane bitonic sort + 32-way merge ----------------
// key = (ordered_uint(value) << 32) | ~index  -> strict total order
// (value desc, index asc). Selection = take global max 20 times, each lane
// consuming from its privately sorted stream.
#define TK_WARPS 4
__global__ void topk_kernel() {
    __shared__ ull sd[TK_WARPS][32][32];
    int w = threadIdx.x >> 5, lane = threadIdx.x & 31;
    int rid = blockIdx.x * TK_WARPS + w;
    const float4* r4 = (const float4*)(g_dist + (size_t)rid * NPTS);

    ull key[32];
    #pragma unroll
    for (int i = 0; i < 8; i++) {
        float4 v = r4[i * 32 + lane];
        int base = i * 128 + lane * 4;
        key[i*4+0] = ((ull)fenc(v.x) << 32) | (unsigned)~(base + 0);
        key[i*4+1] = ((ull)fenc(v.y) << 32) | (unsigned)~(base + 1);
        key[i*4+2] = ((ull)fenc(v.z) << 32) | (unsigned)~(base + 2);
        key[i*4+3] = ((ull)fenc(v.w) << 32) | (unsigned)~(base + 3);
    }
    // bitonic sort ascending (32 elems, fully unrolled)
    #pragma unroll
    for (int k2 = 2; k2 <= 32; k2 <<= 1) {
        #pragma unroll
        for (int j = k2 >> 1; j > 0; j >>= 1) {
            #pragma unroll
            for (int i = 0; i < 32; i++) {
                int l = i ^ j;
                if (l > i) {
                    ull a = key[i], b = key[l];
                    bool sw = ((i & k2) == 0) ? (a > b) : (a < b);
                    if (sw) { key[i] = b; key[l] = a; }
                }
            }
        }
    }
    // spill descending
    #pragma unroll
    for (int i = 0; i < 32; i++) sd[w][i][lane] = key[31 - i];

    ull cur = key[31];
    int cnt = 0;
    int* outp = g_idx + (size_t)rid * KNN_K;
    for (int kk = 0; kk < KNN_K; kk++) {
        ull best = cur;
        #pragma unroll
        for (int off = 16; off; off >>= 1) {
            ull o = __shfl_xor_sync(0xffffffffu, best, off);
            if (o > best) best = o;
        }
        if (lane == 0) outp[kk] = (int)(~(unsigned)best);
        if (cur == best) { cnt++; cur = sd[w][cnt][lane]; }
    }
}

// ---------------- gemmAB: 64(o) x 64(n) tile, writes [n][o] ----------------
__global__ void gemmAB_kernel(const float* __restrict__ x, int cn, int coff, int C, int O,
                              const float* __restrict__ w, const float* __restrict__ g,
                              const float* __restrict__ bias) {
    __shared__ float Wd[16][68], Wl[16][68], Xs[16][68];
    int b = blockIdx.z;
    int o0 = blockIdx.y * 64, n0 = blockIdx.x * 64;
    int t = threadIdx.x, tx = t & 15, ty = t >> 4;
    float aA[4][4] = {}, aB[4][4] = {};
    for (int c0 = 0; c0 < C; c0 += 16) {
        __syncthreads();
        #pragma unroll
        for (int i = 0; i < 4; i++) {
            int idx = t + i * 256;
            int oo = idx >> 4, cc = idx & 15;
            int c = c0 + cc;
            float wd = 0.f, wc = 0.f;
            if (c < C) {
                wd = w[(size_t)(o0 + oo) * 2 * C + c];
                wc = w[(size_t)(o0 + oo) * 2 * C + C + c];
            }
            Wd[cc][oo] = wd; Wl[cc][oo] = wc - wd;
            if (cn) {
                int cc2 = idx >> 6, nn = idx & 63;
                int c2 = c0 + cc2;
                float xv = (c2 < C) ? x[(size_t)b * C * NPTS + (size_t)c2 * NPTS + n0 + nn] : 0.f;
                Xs[cc2][nn] = xv;
            } else {
                int nn = idx >> 4, cc3 = idx & 15;
                int c3 = c0 + cc3;
                float xv = (c3 < C) ? x[((size_t)(b * NPTS) + n0 + nn) * 512 + coff + c3] : 0.f;
                Xs[cc3][nn] = xv;
            }
        }
        __syncthreads();
        #pragma unroll
        for (int cc = 0; cc < 16; cc++) {
            float wa[4], wl[4], xv[4];
            #pragma unroll
            for (int i = 0; i < 4; i++) { wa[i] = Wd[cc][tx + 16 * i]; wl[i] = Wl[cc][tx + 16 * i]; }
            #pragma unroll
            for (int j = 0; j < 4; j++) xv[j] = Xs[cc][ty + 16 * j];
            #pragma unroll
            for (int i = 0; i < 4; i++)
                #pragma unroll
                for (int j = 0; j < 4; j++) { aA[i][j] += wa[i] * xv[j]; aB[i][j] += wl[i] * xv[j]; }
        }
    }
    #pragma unroll
    for (int i = 0; i < 4; i++) {
        int o = o0 + tx + 16 * i;
        float s = g[o] * BNSC, bo = bias[o];
        #pragma unroll
        for (int j = 0; j < 4; j++) {
            int n = n0 + ty + 16 * j;
            size_t base = ((size_t)(b * NPTS) + n) * O + o;
            g_A[base]  = s * aA[i][j];
            g_Bc[base] = s * aB[i][j] + bo;
        }
    }
}

// ---------------- gather (+fused xx of written channels) ----------------
__global__ void gather_kernel(int O, int choff) {
    int w = threadIdx.x >> 5, lane = threadIdx.x & 31;
    int n = blockIdx.x * 8 + w;
    int b = blockIdx.y;
    size_t rowi = (size_t)(b * NPTS) + n;
    const int* ip = g_idx + rowi * KNN_K;
    int iv = (lane < KNN_K) ? ip[lane] : 0;
    int O4 = O >> 2;
    const float4* A4 = (const float4*)g_A + (size_t)(b * NPTS) * O4;
    int npass = (O + 127) / 128;
    float ss = 0.f;
    for (int p = 0; p < npass; p++) {
        int o4 = p * 128 + lane * 4;
        bool act = o4 < O;
        float4 m = make_float4(-INFINITY, -INFINITY, -INFINITY, -INFINITY);
        #pragma unroll
        for (int k = 0; k < KNN_K; k++) {
            int j = __shfl_sync(0xffffffffu, iv, k);
            if (act) {
                float4 a = A4[(size_t)j * O4 + (o4 >> 2)];
                m.x = fmaxf(m.x, a.x); m.y = fmaxf(m.y, a.y);
                m.z = fmaxf(m.z, a.z); m.w = fmaxf(m.w, a.w);
            }
        }
        if (act) {
            float4 bb = *(const float4*)&g_Bc[rowi * O + o4];
            float4 r;
            r.x = m.x + bb.x; r.y = m.y + bb.y; r.z = m.z + bb.z; r.w = m.w + bb.w;
            r.x = r.x > 0.f ? r.x : 0.2f * r.x;
            r.y = r.y > 0.f ? r.y : 0.2f * r.y;
            r.z = r.z > 0.f ? r.z : 0.2f * r.z;
            r.w = r.w > 0.f ? r.w : 0.2f * r.w;
            *(float4*)&g_h[rowi * 512 + choff + o4] = r;
            ss += r.x * r.x + r.y * r.y + r.z * r.z + r.w * r.w;
        }
    }
    #pragma unroll
    for (int off = 16; off; off >>= 1) ss += __shfl_down_sync(0xffffffffu, ss, off);
    if (lane == 0) g_xx[rowi] = ss;
}

// ---------------- init pooled accumulators ----------------
__global__ void initp_kernel() {
    int i = blockIdx.x * 256 + threadIdx.x;
    g_pmax[i] = 0u;
    g_psum[i] = 0.f;
}

// ---------------- gemm5 + fused pooling, double-buffered FFMA2 ----------------
__global__ void gemm5_kernel(const float* __restrict__ w5, const float* __restrict__ g5,
                             const float* __restrict__ b5) {
    __shared__ float Ws[2][16][132], Hs[2][16][132];
    int b = blockIdx.z;
    int o0 = blockIdx.y * 128, n0 = blockIdx.x * 128;
    int t = threadIdx.x, tx = t & 15, ty = t >> 4;
    ull acc[8][4];
    #pragma unroll
    for (int i = 0; i < 8; i++)
        #pragma unroll
        for (int j = 0; j < 4; j++) acc[i][j] = 0ull;

    int nn = t >> 1, cs = (t & 1) * 8;
    const float* hrow = g_h + ((size_t)(b * NPTS) + n0 + nn) * 512 + cs;
    const float* wrow = w5 + (size_t)(o0 + nn) * 512 + cs;
    float4 w0, w1, h0, h1;

    w0 = *(const float4*)wrow; w1 = *(const float4*)(wrow + 4);
    h0 = *(const float4*)hrow; h1 = *(const float4*)(hrow + 4);
    {
        float* dw = &Ws[0][cs][nn]; float* dh = &Hs[0][cs][nn];
        dw[0*132]=w0.x; dw[1*132]=w0.y; dw[2*132]=w0.z; dw[3*132]=w0.w;
        dw[4*132]=w1.x; dw[5*132]=w1.y; dw[6*132]=w1.z; dw[7*132]=w1.w;
        dh[0*132]=h0.x; dh[1*132]=h0.y; dh[2*132]=h0.z; dh[3*132]=h0.w;
        dh[4*132]=h1.x; dh[5*132]=h1.y; dh[6*132]=h1.z; dh[7*132]=h1.w;
    }
    __syncthreads();

    for (int k = 0; k < 32; k++) {
        int kn = k + 1;
        if (kn < 32) {
            const float* qw = wrow + kn * 16;
            const float* qh = hrow + kn * 16;
            w0 = *(const float4*)qw; w1 = *(const float4*)(qw + 4);
            h0 = *(const float4*)qh; h1 = *(const float4*)(qh + 4);
        }
        int p = k & 1;
        #pragma unroll
        for (int cc = 0; cc < 16; cc++) {
            ull a2[8], b2[4];
            #pragma unroll
            for (int i = 0; i < 8; i++) { float av = Ws[p][cc][ty + 16 * i]; a2[i] = pk2(av, av); }
            #pragma unroll
            for (int j = 0; j < 4; j++) b2[j] = *(const ull*)&Hs[p][cc][2 * tx + 32 * j];
            #pragma unroll
            for (int i = 0; i < 8; i++)
                #pragma unroll
                for (int j = 0; j < 4; j++) ffma2(acc[i][j], a2[i], b2[j]);
        }
        if (kn < 32) {
            int q = kn & 1;
            float* dw = &Ws[q][cs][nn]; float* dh = &Hs[q][cs][nn];
            dw[0*132]=w0.x; dw[1*132]=w0.y; dw[2*132]=w0.z; dw[3*132]=w0.w;
            dw[4*132]=w1.x; dw[5*132]=w1.y; dw[6*132]=w1.z; dw[7*132]=w1.w;
            dh[0*132]=h0.x; dh[1*132]=h0.y; dh[2*132]=h0.z; dh[3*132]=h0.w;
            dh[4*132]=h1.x; dh[5*132]=h1.y; dh[6*132]=h1.z; dh[7*132]=h1.w;
        }
        __syncthreads();
    }
    // epilogue: leaky(bn(.)) then fused max/sum pooling over this block's 128 n
    #pragma unroll
    for (int i = 0; i < 8; i++) {
        int o = o0 + ty + 16 * i;
        float s = g5[o] * BNSC, bo = b5[o];
        float mx = -INFINITY, sm = 0.f;
        #pragma unroll
        for (int j = 0; j < 4; j++) {
            float2 v = *(float2*)&acc[i][j];
            v.x = s * v.x + bo; v.y = s * v.y + bo;
            v.x = v.x > 0.f ? v.x : 0.2f * v.x;
            v.y = v.y > 0.f ? v.y : 0.2f * v.y;
            mx = fmaxf(mx, fmaxf(v.x, v.y));
            sm += v.x + v.y;
        }
        #pragma unroll
        for (int off = 8; off; off >>= 1) {
            mx = fmaxf(mx, __shfl_down_sync(0xffffffffu, mx, off, 16));
            sm += __shfl_down_sync(0xffffffffu, sm, off, 16);
        }
        if (tx == 0) {
            atomicMax(&g_pmax[b * 1024 + o], fenc(mx));
            atomicAdd(&g_psum[b * 1024 + o], sm);
        }
    }
}

// ---------------- MLP head ----------------
__global__ void head_kernel(const float* __restrict__ wl1, const float* __restrict__ g6, const float* __restrict__ b6,
                            const float* __restrict__ wl2, const float* __restrict__ g7, const float* __restrict__ b7,
                            const float* __restrict__ wl21, const float* __restrict__ wl22,
                            const float* __restrict__ g8, const float* __restrict__ b8,
                            const float* __restrict__ wl3, float* __restrict__ out) {
    int b = blockIdx.x, t = threadIdx.x;
    __shared__ float sp[2048], s1[256], s2[128], s3[64], s4[32];
    for (int i = t; i < 1024; i += 256) {
        unsigned e = g_pmax[b * 1024 + i];
        unsigned bits = (e & 0x80000000u) ? (e ^ 0x80000000u) : ~e;
        sp[i] = __uint_as_float(bits);
        sp[1024 + i] = g_psum[b * 1024 + i] * (1.f / 1024.f);
    }
    __syncthreads();
    {
        float acc = 0.f;
        const float* wr = wl1 + (size_t)t * 2048;
        for (int c = 0; c < 2048; c++) acc += sp[c] * wr[c];
        acc = g6[t] * (acc * BNSC) + b6[t];
        s1[t] = acc > 0.f ? acc : 0.2f * acc;
    }
    __syncthreads();
    if (t < 128) {
        float acc = 0.f;
        const float* wr = wl2 + (size_t)t * 256;
        for (int c = 0; c < 256; c++) acc += s1[c] * wr[c];
        acc = g7[t] * (acc * BNSC) + b7[t];
        s2[t] = acc > 0.f ? acc : 0.2f * acc;
    }
    __syncthreads();
    if (t < 64) {
        float acc = 0.f;
        const float* wr = wl21 + (size_t)t * 128;
        for (int c = 0; c < 128; c++) acc += s2[c] * wr[c];
        s3[t] = acc;
    }
    __syncthreads();
    if (t < 32) {
        float acc = 0.f;
        const float* wr = wl22 + (size_t)t * 64;
        for (int c = 0; c < 64; c++) acc += s3[c] * wr[c];
        acc = g8[t] * (acc * BNSC) + b8[t];
        s4[t] = 0.5f * acc * (1.0f + erff(acc * 0.70710678118654752f));
    }
    __syncthreads();
    if (t < 90) {
        float acc = 0.f;
        const float* wr = wl3 + (size_t)t * 32;
        for (int c = 0; c < 32; c++) acc += s4[c] * wr[c];
        out[b * 90 + t] = acc;
    }
}

// ---------------- launcher ----------------
extern "C" void kernel_launch(void* const* d_in, const int* in_sizes, int n_in,
                              void* d_out, int out_size) {
    const float* x   = (const float*)d_in[0];
    const float* w1  = (const float*)d_in[2];
    const float* g1  = (const float*)d_in[3];
    const float* b1  = (const float*)d_in[4];
    const float* w2  = (const float*)d_in[5];
    const float* g2  = (const float*)d_in[6];
    const float* b2  = (const float*)d_in[7];
    const float* w3  = (const float*)d_in[8];
    const float* g3  = (const float*)d_in[9];
    const float* b3  = (const float*)d_in[10];
    const float* w4  = (const float*)d_in[11];
    const float* g4  = (const float*)d_in[12];
    const float* b4  = (const float*)d_in[13];
    const float* w5  = (const float*)d_in[14];
    const float* g5  = (const float*)d_in[15];
    const float* b5  = (const float*)d_in[16];
    const float* wl1 = (const float*)d_in[17];
    const float* g6  = (const float*)d_in[18];
    const float* b6  = (const float*)d_in[19];
    const float* wl2 = (const float*)d_in[20];
    const float* g7  = (const float*)d_in[21];
    const float* b7  = (const float*)d_in[22];
    const float* wl21= (const float*)d_in[23];
    const float* wl22= (const float*)d_in[24];
    const float* g8  = (const float*)d_in[25];
    const float* b8  = (const float*)d_in[26];
    const float* wl3 = (const float*)d_in[27];

    initp_kernel<<<BATCH * 1024 / 256, 256>>>();
    xx_cn_kernel<<<dim3(NPTS / 256, BATCH), 256>>>(x);

    struct St { int cn; int coff; int C; int O; int choff;
                const float* w; const float* g; const float* bb; };
    St st[4] = {
        { 1, 0,   6,   64,  0,   w1, g1, b1 },
        { 0, 0,   64,  64,  64,  w2, g2, b2 },
        { 0, 64,  64,  128, 128, w3, g3, b3 },
        { 0, 128, 128, 256, 256, w4, g4, b4 },
    };

    float* gh = nullptr;
    cudaGetSymbolAddress((void**)&gh, g_h);

    for (int s = 0; s < 4; s++) {
        if (st[s].cn)
            dist_cn_kernel<<<dim3(8, 8, BATCH), 256>>>(x);
        else
            dist_nc_kernel<<<dim3(8, 8, BATCH), 256>>>(gh, st[s].coff, st[s].C);
        topk_kernel<<<(BATCH * NPTS) / TK_WARPS, TK_WARPS * 32>>>();
        gemmAB_kernel<<<dim3(16, st[s].O / 64, BATCH), 256>>>(
            st[s].cn ? x : gh, st[s].cn, st[s].coff, st[s].C, st[s].O,
            st[s].w, st[s].g, st[s].bb);
        gather_kernel<<<dim3(NPTS / 8, BATCH), 256>>>(st[s].O, st[s].choff);
    }

    gemm5_kernel<<<dim3(8, 8, BATCH), 256>>>(w5, g5, b5);
    head_kernel <<<BATCH, 256>>>(wl1, g6, b6, wl2, g7, b7, wl21, wl22, g8, b8, wl3,
                                 (float*)d_out);
}